// round 6
// baseline (speedup 1.0000x reference)
#include <cuda_runtime.h>

#define D 128
#define NSEG 256
#define WROWS 256                 // contiguous rows per warp
#define WARPS_PER_BLOCK 4
#define BROWS (WROWS * WARPS_PER_BLOCK)   // 1024 rows per block
#define UNROLL 8

// Scratch accumulators. Zero-initialized at module load; the MLP blocks
// re-zero them at the end of every call, so the zero-on-entry invariant
// holds across the correctness run and all graph replays.
__device__ float g_esum[NSEG * D];
__device__ float g_nsum[NSEG * D];
__device__ float g_ecnt[NSEG];
__device__ float g_ncnt[NSEG];
__device__ unsigned int g_done;      // scatter blocks finished
__device__ unsigned int g_mlp_done;  // mlp blocks finished (for reset handoff)
__device__ float g_sink;             // DCE-proof sink for W1 L2 prefetch

// Per-warp sorted-run segment accumulation with float4 columns.
// Lane l owns columns 4l..4l+3 -> one LDG.128 per row per warp.
__device__ __forceinline__ void scatter_warp(
    const float4* __restrict__ attr4, const float* __restrict__ mask,
    const int* __restrict__ idx, float* __restrict__ gsum,
    float* __restrict__ gcnt, int rs, int re)
{
    if (rs >= re) return;
    const int l = threadIdx.x & 31;

    float4 acc = make_float4(0.f, 0.f, 0.f, 0.f);
    int cur = idx[rs];
    int cnt = 0;

    int r = rs;
    for (; r + UNROLL <= re; r += UNROLL) {
        float4 v[UNROLL];
        float  m[UNROLL];
        int    s[UNROLL];
#pragma unroll
        for (int u = 0; u < UNROLL; u++) {
            v[u] = __ldcs(&attr4[(size_t)(r + u) * 32 + l]);   // read-once stream
            m[u] = mask[r + u];
            s[u] = idx[r + u];
        }
#pragma unroll
        for (int u = 0; u < UNROLL; u++) {
            if (s[u] != cur) {
                atomicAdd(&gsum[cur * D + 4 * l + 0], acc.x);
                atomicAdd(&gsum[cur * D + 4 * l + 1], acc.y);
                atomicAdd(&gsum[cur * D + 4 * l + 2], acc.z);
                atomicAdd(&gsum[cur * D + 4 * l + 3], acc.w);
                if (l == 0) atomicAdd(&gcnt[cur], (float)cnt);
                acc = make_float4(0.f, 0.f, 0.f, 0.f);
                cnt = 0; cur = s[u];
            }
            acc.x += v[u].x * m[u];
            acc.y += v[u].y * m[u];
            acc.z += v[u].z * m[u];
            acc.w += v[u].w * m[u];
            cnt++;
        }
    }
    for (; r < re; r++) {
        int    s = idx[r];
        float  m = mask[r];
        float4 v = __ldcs(&attr4[(size_t)r * 32 + l]);
        if (s != cur) {
            atomicAdd(&gsum[cur * D + 4 * l + 0], acc.x);
            atomicAdd(&gsum[cur * D + 4 * l + 1], acc.y);
            atomicAdd(&gsum[cur * D + 4 * l + 2], acc.z);
            atomicAdd(&gsum[cur * D + 4 * l + 3], acc.w);
            if (l == 0) atomicAdd(&gcnt[cur], (float)cnt);
            acc = make_float4(0.f, 0.f, 0.f, 0.f);
            cnt = 0; cur = s;
        }
        acc.x += v.x * m;
        acc.y += v.y * m;
        acc.z += v.z * m;
        acc.w += v.w * m;
        cnt++;
    }
    atomicAdd(&gsum[cur * D + 4 * l + 0], acc.x);
    atomicAdd(&gsum[cur * D + 4 * l + 1], acc.y);
    atomicAdd(&gsum[cur * D + 4 * l + 2], acc.z);
    atomicAdd(&gsum[cur * D + 4 * l + 3], acc.w);
    if (l == 0) atomicAdd(&gcnt[cur], (float)cnt);
}

// Single fused kernel.
//  blocks [0, NSEG)          : MLP blocks — prefetch weights, spin on g_done,
//                              then compute one graph's output row.
//  blocks [NSEG, NSEG+eb+nb) : scatter blocks (edges first, then nodes).
__global__ __launch_bounds__(128, 8) void fused_kernel(
    const float4* __restrict__ edge4, const float* __restrict__ emask,
    const int* __restrict__ eg,
    const float4* __restrict__ node4, const float* __restrict__ nmask,
    const int* __restrict__ ng,
    const float* __restrict__ global_attr,
    const float* __restrict__ W1, const float* __restrict__ b1,
    const float* __restrict__ W2, const float* __restrict__ b2,
    float* __restrict__ out,
    int E, int N, int eb, int nb)
{
    const int t = threadIdx.x;
    const unsigned total_scatter = (unsigned)(eb + nb);

    if ((int)blockIdx.x >= NSEG) {
        // ---------------- scatter path ----------------
        const int sb = blockIdx.x - NSEG;
        const int w  = t >> 5;
        if (sb < eb) {
            int rs = sb * BROWS + w * WROWS;
            int re = min(rs + WROWS, E);
            scatter_warp(edge4, emask, eg, g_esum, g_ecnt, rs, re);
        } else {
            int rs = (sb - eb) * BROWS + w * WROWS;
            int re = min(rs + WROWS, N);
            scatter_warp(node4, nmask, ng, g_nsum, g_ncnt, rs, re);
        }
        __threadfence();      // make this block's atomics visible
        __syncthreads();
        if (t == 0) atomicAdd(&g_done, 1u);
        return;
    }

    // ---------------- MLP path (one block per graph) ----------------
    const int b = blockIdx.x;

    __shared__ float col[3 * D];
    __shared__ float w2s[32 * D];   // 16 KB
    __shared__ float hp[128];
    __shared__ float h[32];
    __shared__ float b1s[32];

    // --- pre-spin: everything that depends only on inputs ---
    const float4* W24 = (const float4*)W2;
    float4 w2v[8];
#pragma unroll
    for (int i = 0; i < 8; i++) w2v[i] = W24[i * 128 + t];
    float ob = b2[t];
    float ga = global_attr[b * D + t];
    if (t < 32) b1s[t] = b1[t];

    // Touch all of W1 so it's L2-resident when we need it post-spin
    // (the scatter stream evicts it every iteration otherwise).
    float sink = 0.f;
#pragma unroll 4
    for (int k = t; k < 3 * D * 32; k += 128) sink += W1[k];
    if (__float_as_uint(sink) == 0x7fc00001u) g_sink = sink;  // never taken; defeats DCE

#pragma unroll
    for (int i = 0; i < 8; i++) ((float4*)w2s)[i * 128 + t] = w2v[i];

    // --- wait for all scatter blocks ---
    if (t == 0) {
        while (atomicAdd(&g_done, 0u) < total_scatter) __nanosleep(256);
    }
    __syncthreads();
    __threadfence();   // acquire: see scatter's atomics

    // --- collected features ---
    float es = g_esum[b * D + t];
    float ns = g_nsum[b * D + t];
    float ec = fmaxf(g_ecnt[b], 1.f);
    float nc = fmaxf(g_ncnt[b], 1.f);
    col[t]         = ga;
    col[D + t]     = es / ec;
    col[2 * D + t] = ns / nc;

    // Re-zero own sum elements (only this thread reads them).
    g_esum[b * D + t] = 0.f;
    g_nsum[b * D + t] = 0.f;
    __syncthreads();
    // Counts were read by ALL threads above; zero after the sync.
    if (t == 0) { g_ecnt[b] = 0.f; g_ncnt[b] = 0.f; }

    // h[j]: 4 threads per output j, 96 k-rows each, dual accumulators.
    int j    = t & 31;
    int part = t >> 5;
    int k0   = part * 96;
    float p0 = 0.f, p1 = 0.f;
#pragma unroll
    for (int k = 0; k < 96; k += 2) {
        p0 += col[k0 + k]     * W1[(k0 + k) * 32 + j];
        p1 += col[k0 + k + 1] * W1[(k0 + k + 1) * 32 + j];
    }
    hp[t] = p0 + p1;
    __syncthreads();

    if (t < 32)
        h[t] = fmaxf(hp[t] + hp[t + 32] + hp[t + 64] + hp[t + 96] + b1s[t], 0.f);
    __syncthreads();

    float o = ob;
#pragma unroll
    for (int jj = 0; jj < 32; jj++)
        o += h[jj] * w2s[jj * D + t];
    out[b * D + t] = o;

    // --- handoff reset: last MLP block to finish resets the counters.
    // Every MLP block has passed the spin by the time g_mlp_done hits NSEG,
    // so resetting g_done here cannot strand a spinner.
    if (t == 0) {
        unsigned v = atomicAdd(&g_mlp_done, 1u);
        if (v == NSEG - 1u) {
            atomicExch(&g_done, 0u);
            atomicExch(&g_mlp_done, 0u);
        }
    }
}

extern "C" void kernel_launch(void* const* d_in, const int* in_sizes, int n_in,
                              void* d_out, int out_size)
{
    const float* node_attr   = (const float*)d_in[0];
    const float* edge_attr   = (const float*)d_in[1];
    const float* global_attr = (const float*)d_in[2];
    const int*   ng          = (const int*)  d_in[3];
    const int*   eg          = (const int*)  d_in[4];
    const float* nmask       = (const float*)d_in[5];
    const float* emask       = (const float*)d_in[6];
    const float* W1          = (const float*)d_in[7];
    const float* b1          = (const float*)d_in[8];
    const float* W2          = (const float*)d_in[9];
    const float* b2          = (const float*)d_in[10];
    float* out = (float*)d_out;

    int N = in_sizes[3];   // ng_index count
    int E = in_sizes[4];   // eg_index count

    int eb = (E + BROWS - 1) / BROWS;
    int nb = (N + BROWS - 1) / BROWS;

    fused_kernel<<<NSEG + eb + nb, 128>>>(
        (const float4*)edge_attr, emask, eg,
        (const float4*)node_attr, nmask, ng,
        global_attr, W1, b1, W2, b2, out,
        E, N, eb, nb);
}

// round 10
// speedup vs baseline: 1.1082x; 1.1082x over previous
#include <cuda_runtime.h>

#define D 128
#define NSEG 256
#define WROWS 64                  // contiguous rows per warp (fine-grained)
#define WARPS_PER_BLOCK 4
#define BROWS (WROWS * WARPS_PER_BLOCK)   // 256 rows per block
#define UNROLL 8

// Scratch accumulators. Zero-initialized at module load; mlp_kernel re-zeroes
// them at the end of every call, so the zero-on-entry invariant holds across
// the correctness run and all graph replays.
__device__ float g_esum[NSEG * D];
__device__ float g_nsum[NSEG * D];
__device__ float g_ecnt[NSEG];
__device__ float g_ncnt[NSEG];

// Per-warp sorted-run segment accumulation with float4 columns.
// Lane l owns columns 4l..4l+3 -> one LDG.128 per row per warp.
__device__ __forceinline__ void scatter_warp(
    const float4* __restrict__ attr4, const float* __restrict__ mask,
    const int* __restrict__ idx, float* __restrict__ gsum,
    float* __restrict__ gcnt, int rs, int re)
{
    if (rs >= re) return;
    const int l = threadIdx.x & 31;

    float4 acc = make_float4(0.f, 0.f, 0.f, 0.f);
    int cur = idx[rs];
    int cnt = 0;

    int r = rs;
    for (; r + UNROLL <= re; r += UNROLL) {
        float4 v[UNROLL];
        float  m[UNROLL];
        int    s[UNROLL];
#pragma unroll
        for (int u = 0; u < UNROLL; u++) {
            v[u] = attr4[(size_t)(r + u) * 32 + l];
            m[u] = mask[r + u];
            s[u] = idx[r + u];
        }
#pragma unroll
        for (int u = 0; u < UNROLL; u++) {
            if (s[u] != cur) {
                atomicAdd(&gsum[cur * D + 4 * l + 0], acc.x);
                atomicAdd(&gsum[cur * D + 4 * l + 1], acc.y);
                atomicAdd(&gsum[cur * D + 4 * l + 2], acc.z);
                atomicAdd(&gsum[cur * D + 4 * l + 3], acc.w);
                if (l == 0) atomicAdd(&gcnt[cur], (float)cnt);
                acc = make_float4(0.f, 0.f, 0.f, 0.f);
                cnt = 0; cur = s[u];
            }
            acc.x += v[u].x * m[u];
            acc.y += v[u].y * m[u];
            acc.z += v[u].z * m[u];
            acc.w += v[u].w * m[u];
            cnt++;
        }
    }
    for (; r < re; r++) {
        int    s = idx[r];
        float  m = mask[r];
        float4 v = attr4[(size_t)r * 32 + l];
        if (s != cur) {
            atomicAdd(&gsum[cur * D + 4 * l + 0], acc.x);
            atomicAdd(&gsum[cur * D + 4 * l + 1], acc.y);
            atomicAdd(&gsum[cur * D + 4 * l + 2], acc.z);
            atomicAdd(&gsum[cur * D + 4 * l + 3], acc.w);
            if (l == 0) atomicAdd(&gcnt[cur], (float)cnt);
            acc = make_float4(0.f, 0.f, 0.f, 0.f);
            cnt = 0; cur = s;
        }
        acc.x += v.x * m;
        acc.y += v.y * m;
        acc.z += v.z * m;
        acc.w += v.w * m;
        cnt++;
    }
    atomicAdd(&gsum[cur * D + 4 * l + 0], acc.x);
    atomicAdd(&gsum[cur * D + 4 * l + 1], acc.y);
    atomicAdd(&gsum[cur * D + 4 * l + 2], acc.z);
    atomicAdd(&gsum[cur * D + 4 * l + 3], acc.w);
    if (l == 0) atomicAdd(&gcnt[cur], (float)cnt);
}

// Fused grid: first eb blocks handle edges, the rest handle nodes.
__global__ __launch_bounds__(128) void scatter_all(
    const float4* __restrict__ edge4, const float* __restrict__ emask,
    const int* __restrict__ eg,
    const float4* __restrict__ node4, const float* __restrict__ nmask,
    const int* __restrict__ ng,
    int E, int N, int eb)
{
    const int w = threadIdx.x >> 5;
    if ((int)blockIdx.x < eb) {
        int rs = blockIdx.x * BROWS + w * WROWS;
        int re = min(rs + WROWS, E);
        scatter_warp(edge4, emask, eg, g_esum, g_ecnt, rs, re);
    } else {
        int rs = (blockIdx.x - eb) * BROWS + w * WROWS;
        int re = min(rs + WROWS, N);
        scatter_warp(node4, nmask, ng, g_nsum, g_ncnt, rs, re);
    }
}

// One block per graph. Grid-limited occupancy -> register budget is free:
// fully unrolled dual-accumulator h-loop for max loads-in-flight, W2
// prefetched to shared (latency hidden under the h-loop loads).
__global__ void mlp_kernel(
    const float* __restrict__ global_attr,
    const float* __restrict__ W1, const float* __restrict__ b1,
    const float* __restrict__ W2, const float* __restrict__ b2,
    float* __restrict__ out)
{
    int b = blockIdx.x;
    int t = threadIdx.x;

    __shared__ float col[3 * D];
    __shared__ float w2s[32 * D];   // 16 KB
    __shared__ float hp[128];
    __shared__ float h[32];
    __shared__ float b1s[32];

    // Kick off W2 prefetch first (8 float4 per thread, 16 KB total).
    const float4* W24 = (const float4*)W2;
    float4 w2v[8];
#pragma unroll
    for (int i = 0; i < 8; i++) w2v[i] = W24[i * 128 + t];

    // Output bias early (independent load).
    float ob = b2[t];

    // Collected features.
    float ga = global_attr[b * D + t];
    float es = g_esum[b * D + t];
    float ns = g_nsum[b * D + t];
    float ec = fmaxf(g_ecnt[b], 1.f);
    float nc = fmaxf(g_ncnt[b], 1.f);
    col[t]         = ga;
    col[D + t]     = es / ec;
    col[2 * D + t] = ns / nc;
    if (t < 32) b1s[t] = b1[t];

#pragma unroll
    for (int i = 0; i < 8; i++) ((float4*)w2s)[i * 128 + t] = w2v[i];

    // Re-zero own sum elements (only this thread reads them).
    g_esum[b * D + t] = 0.f;
    g_nsum[b * D + t] = 0.f;
    __syncthreads();

    // Counts were read by ALL threads above; safe to zero only after the sync.
    if (t == 0) { g_ecnt[b] = 0.f; g_ncnt[b] = 0.f; }

    // h[j]: 4 threads per output j, 96 k-rows each, dual accumulators.
    int j    = t & 31;
    int part = t >> 5;
    int k0   = part * 96;
    float p0 = 0.f, p1 = 0.f;
#pragma unroll
    for (int k = 0; k < 96; k += 2) {
        p0 += col[k0 + k]     * W1[(k0 + k) * 32 + j];
        p1 += col[k0 + k + 1] * W1[(k0 + k + 1) * 32 + j];
    }
    hp[t] = p0 + p1;
    __syncthreads();

    if (t < 32)
        h[t] = fmaxf(hp[t] + hp[t + 32] + hp[t + 64] + hp[t + 96] + b1s[t], 0.f);
    __syncthreads();

    float o = ob;
#pragma unroll
    for (int jj = 0; jj < 32; jj++)
        o += h[jj] * w2s[jj * D + t];
    out[b * D + t] = o;
}

extern "C" void kernel_launch(void* const* d_in, const int* in_sizes, int n_in,
                              void* d_out, int out_size)
{
    const float* node_attr   = (const float*)d_in[0];
    const float* edge_attr   = (const float*)d_in[1];
    const float* global_attr = (const float*)d_in[2];
    const int*   ng          = (const int*)  d_in[3];
    const int*   eg          = (const int*)  d_in[4];
    const float* nmask       = (const float*)d_in[5];
    const float* emask       = (const float*)d_in[6];
    const float* W1          = (const float*)d_in[7];
    const float* b1          = (const float*)d_in[8];
    const float* W2          = (const float*)d_in[9];
    const float* b2          = (const float*)d_in[10];
    float* out = (float*)d_out;

    int N = in_sizes[3];   // ng_index count
    int E = in_sizes[4];   // eg_index count

    int eb = (E + BROWS - 1) / BROWS;
    int nb = (N + BROWS - 1) / BROWS;

    scatter_all<<<eb + nb, 128>>>((const float4*)edge_attr, emask, eg,
                                  (const float4*)node_attr, nmask, ng,
                                  E, N, eb);
    mlp_kernel<<<NSEG, 128>>>(global_attr, W1, b1, W2, b2, out);
}